// round 12
// baseline (speedup 1.0000x reference)
#include <cuda_runtime.h>
#include <cstdint>
#include <cstddef>

#define BATCH    64
#define SEQ      2048
#define INPUT    8
#define HIDDEN   512
#define NUM_SEEDS 4
#define DD       12
#define OUTK     10
#define ALPHA_F  0.1f
#define K1_F     (0.1f * (500.0f/512.0f))
#define QSCALE   131072.0f           /* 2^17 fixed-point scale (magic-round safe) */
#define QINV     (1.0f/131072.0f)
#define MAGIC_F  12582912.0f         /* 1.5 * 2^23 */
#define MAGIC_I  0x4B400000

typedef unsigned long long u64;

// ---------------- scratch (static __device__ — no allocation) ----------------
__device__ float g_m0[NUM_SEEDS][HIDDEN];
__device__ float g_m1[NUM_SEEDS][HIDDEN];
__device__ float g_n0[NUM_SEEDS][HIDDEN];
__device__ float g_n1[NUM_SEEDS][HIDDEN];
__device__ float g_I [NUM_SEEDS][HIDDEN][INPUT];

__device__ __forceinline__ float fast_tanh(float x) {
    float r;
    asm("tanh.approx.f32 %0, %1;" : "=f"(r) : "f"(x));
    return r;
}
__device__ __forceinline__ u64 pk2(float lo, float hi) {
    u64 r;
    asm("mov.b64 %0, {%1, %2};" : "=l"(r) : "f"(lo), "f"(hi));
    return r;
}
__device__ __forceinline__ float2 up2(u64 v) {
    float2 r;
    asm("mov.b64 {%0, %1}, %2;" : "=f"(r.x), "=f"(r.y) : "l"(v));
    return r;
}
__device__ __forceinline__ u64 fma2(u64 a, u64 b, u64 c) {
    u64 r;
    asm("fma.rn.f32x2 %0, %1, %2, %3;" : "=l"(r) : "l"(a), "l"(b), "l"(c));
    return r;
}
__device__ __forceinline__ int magic_rni(float x) {
    return __float_as_int(x + MAGIC_F) - MAGIC_I;
}
__device__ __forceinline__ float magic_itf(int s) {
    return __int_as_float(s + MAGIC_I) - MAGIC_F;
}

// ---------------- kernel 1: combined mixture -> m, n, I ----------------
__global__ void setup_kernel(const float* __restrict__ means,
                             const float* __restrict__ L,
                             const float* __restrict__ mw,
                             const float* __restrict__ seeds) {
    __shared__ float Lc[DD][DD];
    __shared__ float mc[DD];
    int tid = threadIdx.x;

    float w0 = fmaxf(mw[0], 1e-6f);
    float w1 = fmaxf(mw[1], 1e-6f);
    float inv = 1.0f / (w0 + w1);
    w0 *= inv; w1 *= inv;

    if (tid < DD * DD) {
        int d = tid / DD, e = tid - d * DD;
        float a = L[d * DD + e];
        float c = L[DD * DD + d * DD + e];
        float v = 0.0f;
        if (e < d) {
            v = w0 * a + w1 * c;
        } else if (e == d) {
            v = w0 * (fabsf(a - 1e-12f) + 1e-12f)
              + w1 * (fabsf(c - 1e-12f) + 1e-12f);
        }
        Lc[d][e] = v;
    }
    if (tid < DD) mc[tid] = w0 * means[tid] + w1 * means[DD + tid];
    __syncthreads();

    int g = blockIdx.x * blockDim.x + tid;
    int s = g >> 9, h = g & 511;

    float sd[DD];
    #pragma unroll
    for (int e = 0; e < DD; e++) sd[e] = seeds[(size_t)g * DD + e];

    float comb[DD];
    #pragma unroll
    for (int d = 0; d < DD; d++) {
        float v = mc[d];
        for (int e = 0; e <= d; e++) v = fmaf(Lc[d][e], sd[e], v);
        comb[d] = v;
    }
    g_m0[s][h] = comb[0];
    g_m1[s][h] = comb[1];
    g_n0[s][h] = comb[2];
    g_n1[s][h] = comb[3];
    #pragma unroll
    for (int i = 0; i < INPUT; i++) g_I[s][h][i] = comb[4 + i];
}

// ---------------- kernel 2: output channels 2..9 (x-only, via pinv@span == I) ----
__global__ __launch_bounds__(32) void xout_kernel(const float* __restrict__ x,
                                                  float* __restrict__ out) {
    const int b = blockIdx.x;
    const int lane = threadIdx.x;
    if (lane >= INPUT) return;

    const float* src = x + (size_t)b * SEQ * INPUT + lane;
    float* ob = out + (size_t)b * SEQ * OUTK + 2 + lane;

    float acc = 0.0f;
    #pragma unroll 8
    for (int t = 0; t < SEQ; t++) {
        acc = fmaf(0.9f, acc, ALPHA_F * src[(size_t)t * INPUT]);
        ob[(size_t)t * OUTK] = acc;
    }
}

// ---------------- kernel 3: TWO interleaved RNN chains per block ----------------
// 128 threads; each thread owns 4 hidden units of chain 0 (batch 2B) AND 4 of
// chain 1 (batch 2B+1). Both chain-fronts run back-to-back in one stream (chain
// 1's work fills chain 0's redux/MUFU shadows); ONE __syncthreads serves both
// exchanges, halving the per-step synchronization floor.
__global__ __launch_bounds__(128, 1) void rnn_kernel(const float* __restrict__ x,
                                                     const int* __restrict__ cur_seeds,
                                                     float* __restrict__ out) {
    const int tid = threadIdx.x;
    const int wid = tid >> 5, lane = tid & 31;
    const int h0 = tid * 4;
    const float KQ = K1_F * QINV;
    const float K1S = K1_F * QINV;
    const u64 C9 = pk2(0.9f, 0.9f);
    const u64 ZU = 0ull;

    // ---- per-chain persistent state (token-pasted via S suffix) ----
    #define CHAIN_DECL(S)                                                         \
        const int b_##S = blockIdx.x * 2 + S;                                     \
        const int s_##S = cur_seeds[b_##S];                                       \
        float4 n0_##S = *(const float4*)&g_n0[s_##S][h0];                         \
        float4 n1_##S = *(const float4*)&g_n1[s_##S][h0];                         \
        n0_##S.x *= QSCALE; n0_##S.y *= QSCALE;                                   \
        n0_##S.z *= QSCALE; n0_##S.w *= QSCALE;                                   \
        n1_##S.x *= QSCALE; n1_##S.y *= QSCALE;                                   \
        n1_##S.z *= QSCALE; n1_##S.w *= QSCALE;                                   \
        float4 m0_##S = *(const float4*)&g_m0[s_##S][h0];                         \
        float4 m1_##S = *(const float4*)&g_m1[s_##S][h0];                         \
        const u64 M0A_##S = pk2(m0_##S.x * KQ, m0_##S.y * KQ);                    \
        const u64 M0B_##S = pk2(m0_##S.z * KQ, m0_##S.w * KQ);                    \
        const u64 M1A_##S = pk2(m1_##S.x * KQ, m1_##S.y * KQ);                    \
        const u64 M1B_##S = pk2(m1_##S.z * KQ, m1_##S.w * KQ);                    \
        u64 WA_##S[INPUT], WB_##S[INPUT];                                         \
        _Pragma("unroll")                                                         \
        for (int i = 0; i < INPUT; i++) {                                         \
            WA_##S[i] = pk2(ALPHA_F * g_I[s_##S][h0 + 0][i],                      \
                            ALPHA_F * g_I[s_##S][h0 + 1][i]);                     \
            WB_##S[i] = pk2(ALPHA_F * g_I[s_##S][h0 + 2][i],                      \
                            ALPHA_F * g_I[s_##S][h0 + 3][i]);                     \
        }                                                                         \
        const float* xb_##S = x + (size_t)b_##S * SEQ * INPUT;                    \
        float2* ob_##S = (float2*)(out + (size_t)b_##S * SEQ * OUTK);             \
        u64 hA_##S = ZU, hB_##S = ZU;                                             \
        float oa_##S = 0.0f, ov_##S = 0.0f;                                       \
        float4 xA_##S = *(const float4*)(xb_##S + 0);                             \
        float4 xB_##S = *(const float4*)(xb_##S + 4);

    CHAIN_DECL(0)
    CHAIN_DECL(1)
    #undef CHAIN_DECL

    __shared__ __align__(16) u64 isp[2][2][4];   // [parity][chain][warp]

    // front: tanh -> q-dot -> magic round -> redux -> STS; then shadow aix+decay
    #define FRONT(S, par)                                                         \
    {                                                                             \
        float2 hx = up2(hA_##S), hy = up2(hB_##S);                                \
        float th0 = fast_tanh(hx.x);                                              \
        float th1 = fast_tanh(hx.y);                                              \
        float th2 = fast_tanh(hy.x);                                              \
        float th3 = fast_tanh(hy.y);                                              \
        float q0 = fmaf(n0_##S.x, th0, n0_##S.y * th1)                            \
                 + fmaf(n0_##S.z, th2, n0_##S.w * th3);                           \
        float q1 = fmaf(n1_##S.x, th0, n1_##S.y * th1)                            \
                 + fmaf(n1_##S.z, th2, n1_##S.w * th3);                           \
        int iq0 = magic_rni(q0);                                                  \
        int iq1 = magic_rni(q1);                                                  \
        iq0 = __reduce_add_sync(0xffffffffu, iq0);                                \
        iq1 = __reduce_add_sync(0xffffffffu, iq1);                                \
        if (lane == 0)                                                            \
            isp[par][S][wid] = ((u64)(unsigned)iq0 << 32) | (unsigned)iq1;        \
        u64 xd0 = pk2(xA_##S.x, xA_##S.x), xd1 = pk2(xA_##S.y, xA_##S.y);         \
        u64 xd2 = pk2(xA_##S.z, xA_##S.z), xd3 = pk2(xA_##S.w, xA_##S.w);         \
        u64 xd4 = pk2(xB_##S.x, xB_##S.x), xd5 = pk2(xB_##S.y, xB_##S.y);         \
        u64 xd6 = pk2(xB_##S.z, xB_##S.z), xd7 = pk2(xB_##S.w, xB_##S.w);         \
        u64 aA = fma2(WA_##S[0], xd0, ZU);                                        \
        u64 aB = fma2(WB_##S[0], xd0, ZU);                                        \
        aA = fma2(WA_##S[1], xd1, aA);  aB = fma2(WB_##S[1], xd1, aB);            \
        aA = fma2(WA_##S[2], xd2, aA);  aB = fma2(WB_##S[2], xd2, aB);            \
        aA = fma2(WA_##S[3], xd3, aA);  aB = fma2(WB_##S[3], xd3, aB);            \
        aA = fma2(WA_##S[4], xd4, aA);  aB = fma2(WB_##S[4], xd4, aB);            \
        aA = fma2(WA_##S[5], xd5, aA);  aB = fma2(WB_##S[5], xd5, aB);            \
        aA = fma2(WA_##S[6], xd6, aA);  aB = fma2(WB_##S[6], xd6, aB);            \
        aA = fma2(WA_##S[7], xd7, aA);  aB = fma2(WB_##S[7], xd7, aB);            \
        hA_##S = fma2(C9, hA_##S, aA);   /* h' = 0.9h + aix (p-independent) */    \
        hB_##S = fma2(C9, hB_##S, aB);                                            \
    }

    // post: combine warp partials, magic int->float, rank-2 update, out scan
    #define POST(S, par, T)                                                       \
    {                                                                             \
        ulonglong2 w01 = *(const ulonglong2*)&isp[par][S][0];                     \
        ulonglong2 w23 = *(const ulonglong2*)&isp[par][S][2];                     \
        int s0 = (int)(unsigned)(w01.x >> 32) + (int)(unsigned)(w01.y >> 32)      \
               + (int)(unsigned)(w23.x >> 32) + (int)(unsigned)(w23.y >> 32);     \
        int s1 = (int)(unsigned)w01.x + (int)(unsigned)w01.y                      \
               + (int)(unsigned)w23.x + (int)(unsigned)w23.y;                     \
        float p0 = magic_itf(s0);                                                 \
        float p1 = magic_itf(s1);                                                 \
        u64 p0d = pk2(p0, p0), p1d = pk2(p1, p1);                                 \
        hA_##S = fma2(M0A_##S, p0d, fma2(M1A_##S, p1d, hA_##S));                  \
        hB_##S = fma2(M0B_##S, p0d, fma2(M1B_##S, p1d, hB_##S));                  \
        oa_##S = fmaf(0.9f, oa_##S, K1S * p0);                                    \
        ov_##S = fmaf(0.9f, ov_##S, K1S * p1);                                    \
        if (tid == 96 + S)                                                        \
            ob_##S[(size_t)(T) * (OUTK / 2)] = make_float2(oa_##S, ov_##S);       \
    }

    for (int t = 0; t < SEQ; t++) {
        const int par = t & 1;
        // prefetch next x row for both chains (broadcast loads, off chain)
        int tn = (t + 1 < SEQ) ? t + 1 : t;
        float4 nA0 = *(const float4*)(xb_0 + (size_t)tn * INPUT);
        float4 nB0 = *(const float4*)(xb_0 + (size_t)tn * INPUT + 4);
        float4 nA1 = *(const float4*)(xb_1 + (size_t)tn * INPUT);
        float4 nB1 = *(const float4*)(xb_1 + (size_t)tn * INPUT + 4);

        FRONT(0, par)
        FRONT(1, par)
        __syncthreads();          // ONE barrier for both chains
        POST(0, par, t)
        POST(1, par, t)

        xA_0 = nA0; xB_0 = nB0;
        xA_1 = nA1; xB_1 = nB1;
    }
    #undef FRONT
    #undef POST
}

// ---------------- launch ----------------
extern "C" void kernel_launch(void* const* d_in, const int* in_sizes, int n_in,
                              void* d_out, int out_size) {
    const float* x     = (const float*)d_in[0];   // (64,2048,8)
    const float* means = (const float*)d_in[1];   // (2,12)
    const float* L     = (const float*)d_in[2];   // (2,12,12)
    const float* mw    = (const float*)d_in[3];   // (2,)
    const float* seeds = (const float*)d_in[4];   // (4,512,12)
    const int*   cs    = (const int*)d_in[5];     // (64,)
    float* out = (float*)d_out;                   // (64,2048,10)

    setup_kernel<<<8, 256>>>(means, L, mw, seeds);
    xout_kernel<<<BATCH, 32>>>(x, out);
    rnn_kernel<<<BATCH / 2, 128>>>(x, cs, out);
}

// round 13
// speedup vs baseline: 1.8596x; 1.8596x over previous
#include <cuda_runtime.h>
#include <cstdint>
#include <cstddef>

#define BATCH    64
#define SEQ      2048
#define INPUT    8
#define HIDDEN   512
#define NUM_SEEDS 4
#define DD       12
#define OUTK     10
#define ALPHA_F  0.1f
#define K1_F     (0.1f * (500.0f/512.0f))
#define QSCALE   4194304.0f          /* 2^22 fixed-point scale for warp reduction */
#define QINV     (1.0f/4194304.0f)

typedef unsigned long long u64;

// ---------------- scratch (static __device__ — no allocation) ----------------
__device__ float g_m0[NUM_SEEDS][HIDDEN];
__device__ float g_m1[NUM_SEEDS][HIDDEN];
__device__ float g_n0[NUM_SEEDS][HIDDEN];
__device__ float g_n1[NUM_SEEDS][HIDDEN];
__device__ float g_I [NUM_SEEDS][HIDDEN][INPUT];

// native tanh (MUFU.TANH): 1 MUFU op, ~16cyc; rel err ~2^-11.
__device__ __forceinline__ float fast_tanh(float x) {
    float r;
    asm("tanh.approx.f32 %0, %1;" : "=f"(r) : "f"(x));
    return r;
}

// ---- packed f32x2 helpers (Blackwell FFMA2 via PTX) ----
__device__ __forceinline__ u64 pk2(float lo, float hi) {
    u64 r;
    asm("mov.b64 %0, {%1, %2};" : "=l"(r) : "f"(lo), "f"(hi));
    return r;
}
__device__ __forceinline__ float2 up2(u64 v) {
    float2 r;
    asm("mov.b64 {%0, %1}, %2;" : "=f"(r.x), "=f"(r.y) : "l"(v));
    return r;
}
__device__ __forceinline__ u64 fma2(u64 a, u64 b, u64 c) {
    u64 r;
    asm("fma.rn.f32x2 %0, %1, %2, %3;" : "=l"(r) : "l"(a), "l"(b), "l"(c));
    return r;
}

// ---------------- kernel 1: combined mixture -> m, n, I ----------------
__global__ void setup_kernel(const float* __restrict__ means,
                             const float* __restrict__ L,
                             const float* __restrict__ mw,
                             const float* __restrict__ seeds) {
    __shared__ float Lc[DD][DD];
    __shared__ float mc[DD];
    int tid = threadIdx.x;

    float w0 = fmaxf(mw[0], 1e-6f);
    float w1 = fmaxf(mw[1], 1e-6f);
    float inv = 1.0f / (w0 + w1);
    w0 *= inv; w1 *= inv;

    if (tid < DD * DD) {
        int d = tid / DD, e = tid - d * DD;
        float a = L[d * DD + e];
        float c = L[DD * DD + d * DD + e];
        float v = 0.0f;
        if (e < d) {
            v = w0 * a + w1 * c;
        } else if (e == d) {
            v = w0 * (fabsf(a - 1e-12f) + 1e-12f)
              + w1 * (fabsf(c - 1e-12f) + 1e-12f);
        }
        Lc[d][e] = v;
    }
    if (tid < DD) mc[tid] = w0 * means[tid] + w1 * means[DD + tid];
    __syncthreads();

    int g = blockIdx.x * blockDim.x + tid;      // 0..2047 = s*512 + h
    int s = g >> 9, h = g & 511;

    float sd[DD];
    #pragma unroll
    for (int e = 0; e < DD; e++) sd[e] = seeds[(size_t)g * DD + e];

    float comb[DD];
    #pragma unroll
    for (int d = 0; d < DD; d++) {
        float v = mc[d];
        for (int e = 0; e <= d; e++) v = fmaf(Lc[d][e], sd[e], v);
        comb[d] = v;
    }
    g_m0[s][h] = comb[0];
    g_m1[s][h] = comb[1];
    g_n0[s][h] = comb[2];
    g_n1[s][h] = comb[3];
    #pragma unroll
    for (int i = 0; i < INPUT; i++) g_I[s][h][i] = comb[4 + i];
}

// ---------------- kernel 2: the sequential RNN scan + FULL output row ----------------
// R10 skeleton (128 thr, redux fixed-point 2^22, STS/BAR/LDS exchange, f32x2,
// 2-step unroll) with the xout kernel FUSED in: every step, warp-3 lanes 0..9
// store the complete out[b][t][0..9] row (40B coalesced). Lanes 0,1 use the
// rank-coefficient leaky scans (computed redundantly by all threads); lanes
// 2..9 run the x-only scan acc = 0.9*acc + 0.1*x_t[lane-2], bit-identical to
// the old xout_kernel. This removes a serialized ~2048-iteration kernel from
// the critical path.
__global__ __launch_bounds__(128, 1) void rnn_kernel(const float* __restrict__ x,
                                                     const int* __restrict__ cur_seeds,
                                                     float* __restrict__ out) {
    const int b = blockIdx.x;
    const int tid = threadIdx.x;
    const int wid = tid >> 5, lane = tid & 31;
    const int s = cur_seeds[b];
    const int h0 = tid * 4;

    // n prescaled by 2^22 (scalar — q-dot consumes scalar tanh outputs)
    float4 N0 = *(const float4*)&g_n0[s][h0];
    float4 N1 = *(const float4*)&g_n1[s][h0];
    N0.x *= QSCALE; N0.y *= QSCALE; N0.z *= QSCALE; N0.w *= QSCALE;
    N1.x *= QSCALE; N1.y *= QSCALE; N1.z *= QSCALE; N1.w *= QSCALE;

    // m packed over unit pairs, K1*2^-22 folded in
    const float KQ = K1_F * QINV;
    float4 m0 = *(const float4*)&g_m0[s][h0];
    float4 m1 = *(const float4*)&g_m1[s][h0];
    const u64 M0A = pk2(m0.x * KQ, m0.y * KQ);
    const u64 M0B = pk2(m0.z * KQ, m0.w * KQ);
    const u64 M1A = pk2(m1.x * KQ, m1.y * KQ);
    const u64 M1B = pk2(m1.z * KQ, m1.w * KQ);

    // I packed over unit pairs, ALPHA folded in
    u64 IwA[INPUT], IwB[INPUT];
    #pragma unroll
    for (int i = 0; i < INPUT; i++) {
        IwA[i] = pk2(ALPHA_F * g_I[s][h0 + 0][i], ALPHA_F * g_I[s][h0 + 1][i]);
        IwB[i] = pk2(ALPHA_F * g_I[s][h0 + 2][i], ALPHA_F * g_I[s][h0 + 3][i]);
    }

    const float* xb = x + (size_t)b * SEQ * INPUT;
    float* ob = out + (size_t)b * SEQ * OUTK;     // full output rows
    const float K1S = K1_F * QINV;
    const u64 C9 = pk2(0.9f, 0.9f);
    const u64 ZU = 0ull;

    __shared__ __align__(16) u64 isp[2][4];       // [parity][warp]: {iq0,iq1}

    u64 hA = ZU, hB = ZU;                         // packed (h0,h1),(h2,h3)
    float oa = 0.0f, obv = 0.0f;                  // rank scans (all threads)
    float accx = 0.0f;                            // x-only scan (lanes 2..9 of warp 3)
    const bool store_lane = (wid == 3) && (lane < OUTK);
    const bool is0 = (lane == 0), is1 = (lane == 1);
    const float* xgl = xb + ((lane - 2) & 7);     // this lane's x column

    float4 xA0 = *(const float4*)(xb + 0), xB0 = *(const float4*)(xb + 4);
    float4 xA1 = *(const float4*)(xb + 8), xB1 = *(const float4*)(xb + 12);

    #define RNN_STEP(PAR, T, XA, XB)                                              \
    {                                                                             \
        /* x column for the fused output scan (L1 broadcast hit, off-chain) */    \
        float xg = ALPHA_F * xgl[(size_t)(T) * INPUT];                            \
        float2 hx = up2(hA), hy = up2(hB);                                        \
        float th0 = fast_tanh(hx.x);                                              \
        float th1 = fast_tanh(hx.y);                                              \
        float th2 = fast_tanh(hy.x);                                              \
        float th3 = fast_tanh(hy.y);                                              \
        float q0 = fmaf(N0.x, th0, N0.y * th1) + fmaf(N0.z, th2, N0.w * th3);     \
        float q1 = fmaf(N1.x, th0, N1.y * th1) + fmaf(N1.z, th2, N1.w * th3);     \
        int iq0 = __float2int_rn(q0);                                             \
        int iq1 = __float2int_rn(q1);                                             \
        iq0 = __reduce_add_sync(0xffffffffu, iq0);                                \
        iq1 = __reduce_add_sync(0xffffffffu, iq1);                                \
        if (lane == 0)                                                            \
            isp[PAR][wid] = ((u64)(unsigned)iq0 << 32) | (unsigned)iq1;           \
        /* shadow work: aix + decay applied to h (p-independent) */               \
        u64 xd0 = pk2(XA.x, XA.x), xd1 = pk2(XA.y, XA.y);                         \
        u64 xd2 = pk2(XA.z, XA.z), xd3 = pk2(XA.w, XA.w);                         \
        u64 xd4 = pk2(XB.x, XB.x), xd5 = pk2(XB.y, XB.y);                         \
        u64 xd6 = pk2(XB.z, XB.z), xd7 = pk2(XB.w, XB.w);                         \
        u64 aA = fma2(IwA[0], xd0, ZU);                                           \
        u64 aB = fma2(IwB[0], xd0, ZU);                                           \
        aA = fma2(IwA[1], xd1, aA);  aB = fma2(IwB[1], xd1, aB);                  \
        aA = fma2(IwA[2], xd2, aA);  aB = fma2(IwB[2], xd2, aB);                  \
        aA = fma2(IwA[3], xd3, aA);  aB = fma2(IwB[3], xd3, aB);                  \
        aA = fma2(IwA[4], xd4, aA);  aB = fma2(IwB[4], xd4, aB);                  \
        aA = fma2(IwA[5], xd5, aA);  aB = fma2(IwB[5], xd5, aB);                  \
        aA = fma2(IwA[6], xd6, aA);  aB = fma2(IwB[6], xd6, aB);                  \
        aA = fma2(IwA[7], xd7, aA);  aB = fma2(IwB[7], xd7, aB);                  \
        hA = fma2(C9, hA, aA);   /* h' = 0.9h + aix (p-independent) */            \
        hB = fma2(C9, hB, aB);                                                    \
        /* x-only output scan (bit-identical to old xout_kernel) */              \
        accx = fmaf(0.9f, accx, xg);                                              \
        __syncthreads();                                                          \
        ulonglong2 w01 = *(const ulonglong2*)&isp[PAR][0];                        \
        ulonglong2 w23 = *(const ulonglong2*)&isp[PAR][2];                        \
        int s0 = (int)(unsigned)(w01.x >> 32) + (int)(unsigned)(w01.y >> 32)      \
               + (int)(unsigned)(w23.x >> 32) + (int)(unsigned)(w23.y >> 32);     \
        int s1 = (int)(unsigned)w01.x + (int)(unsigned)w01.y                      \
               + (int)(unsigned)w23.x + (int)(unsigned)w23.y;                     \
        float p0 = (float)s0;                                                     \
        float p1 = (float)s1;                                                     \
        u64 p0d = pk2(p0, p0), p1d = pk2(p1, p1);                                 \
        hA = fma2(M0A, p0d, fma2(M1A, p1d, hA));                                  \
        hB = fma2(M0B, p0d, fma2(M1B, p1d, hB));                                  \
        oa  = fmaf(0.9f, oa,  K1S * p0);   /* all threads: symmetric streams */   \
        obv = fmaf(0.9f, obv, K1S * p1);                                          \
        float oval = is0 ? oa : (is1 ? obv : accx);                               \
        if (store_lane) ob[(size_t)(T) * OUTK + lane] = oval;                     \
    }

    for (int t = 0; t < SEQ; t += 2) {
        int tf = (t + 2 <= SEQ - 2) ? t + 2 : SEQ - 2;
        float4 nA0 = *(const float4*)(xb + (size_t)tf * INPUT);
        float4 nB0 = *(const float4*)(xb + (size_t)tf * INPUT + 4);
        float4 nA1 = *(const float4*)(xb + (size_t)(tf + 1) * INPUT);
        float4 nB1 = *(const float4*)(xb + (size_t)(tf + 1) * INPUT + 4);

        RNN_STEP(0, t,     xA0, xB0);
        RNN_STEP(1, t + 1, xA1, xB1);

        xA0 = nA0; xB0 = nB0; xA1 = nA1; xB1 = nB1;
    }
    #undef RNN_STEP
}

// ---------------- launch ----------------
extern "C" void kernel_launch(void* const* d_in, const int* in_sizes, int n_in,
                              void* d_out, int out_size) {
    const float* x     = (const float*)d_in[0];   // (64,2048,8)
    const float* means = (const float*)d_in[1];   // (2,12)
    const float* L     = (const float*)d_in[2];   // (2,12,12)
    const float* mw    = (const float*)d_in[3];   // (2,)
    const float* seeds = (const float*)d_in[4];   // (4,512,12)
    const int*   cs    = (const int*)d_in[5];     // (64,)
    float* out = (float*)d_out;                   // (64,2048,10)

    setup_kernel<<<8, 256>>>(means, L, mw, seeds);
    rnn_kernel<<<BATCH, 128>>>(x, cs, out);
}

// round 15
// speedup vs baseline: 1.8752x; 1.0084x over previous
#include <cuda_runtime.h>
#include <cstdint>
#include <cstddef>

#define BATCH    64
#define SEQ      2048
#define INPUT    8
#define HIDDEN   512
#define NUM_SEEDS 4
#define DD       12
#define OUTK     10
#define ALPHA_F  0.1f
#define K1_F     (0.1f * (500.0f/512.0f))
#define QSCALE   4194304.0f          /* 2^22 fixed-point scale for warp reduction */
#define QINV     (1.0f/4194304.0f)

typedef unsigned long long u64;

// native tanh (MUFU.TANH): 1 MUFU op, ~16cyc; rel err ~2^-11.
__device__ __forceinline__ float fast_tanh(float x) {
    float r;
    asm("tanh.approx.f32 %0, %1;" : "=f"(r) : "f"(x));
    return r;
}

// ---- packed f32x2 helpers (Blackwell FFMA2 via PTX) ----
__device__ __forceinline__ u64 pk2(float lo, float hi) {
    u64 r;
    asm("mov.b64 %0, {%1, %2};" : "=l"(r) : "f"(lo), "f"(hi));
    return r;
}
__device__ __forceinline__ float2 up2(u64 v) {
    float2 r;
    asm("mov.b64 {%0, %1}, %2;" : "=f"(r.x), "=f"(r.y) : "l"(v));
    return r;
}
__device__ __forceinline__ u64 fma2(u64 a, u64 b, u64 c) {
    u64 r;
    asm("fma.rn.f32x2 %0, %1, %2, %3;" : "=l"(r) : "l"(a), "l"(b), "l"(c));
    return r;
}

// ---------------- single fused kernel ----------------
// Prologue (one-time, per block): compute the mixture-combined clamped
// Cholesky Lc (12x12, in smem — STRIDED init, 128 threads cover 144 entries),
// then each thread derives comb[12] = Lc @ seed + mc for its 4 hidden units
// -> M/N/Iw regs. Main loop: R13's proven RNN scan (redux fixed-point 2^22,
// STS/BAR/LDS exchange, f32x2 elementwise, fused full-output-row store).
__global__ __launch_bounds__(128, 1) void rnn_kernel(const float* __restrict__ x,
                                                     const float* __restrict__ means,
                                                     const float* __restrict__ L,
                                                     const float* __restrict__ mw,
                                                     const float* __restrict__ seeds,
                                                     const int* __restrict__ cur_seeds,
                                                     float* __restrict__ out) {
    const int b = blockIdx.x;
    const int tid = threadIdx.x;
    const int wid = tid >> 5, lane = tid & 31;
    const int s = cur_seeds[b];
    const int h0 = tid * 4;

    // ---- prologue: mixture-combined Lc, mc (identical math to old setup) ----
    __shared__ float Lc[DD][DD];
    __shared__ float mc[DD];
    {
        float w0 = fmaxf(mw[0], 1e-6f);
        float w1 = fmaxf(mw[1], 1e-6f);
        float inv = 1.0f / (w0 + w1);
        w0 *= inv; w1 *= inv;

        // STRIDED: 128 threads must cover all 144 entries (R14 bug fix)
        for (int i = tid; i < DD * DD; i += 128) {
            int d = i / DD, e = i - d * DD;
            float a = L[d * DD + e];
            float c = L[DD * DD + d * DD + e];
            float v = 0.0f;
            if (e < d) {
                v = w0 * a + w1 * c;
            } else if (e == d) {
                v = w0 * (fabsf(a - 1e-12f) + 1e-12f)
                  + w1 * (fabsf(c - 1e-12f) + 1e-12f);
            }
            Lc[d][e] = v;
        }
        if (tid < DD) mc[tid] = w0 * means[tid] + w1 * means[DD + tid];
    }
    __syncthreads();

    // per-thread comb for 4 hidden units -> m0,m1,n0,n1,I
    float m0v[4], m1v[4], n0v[4], n1v[4], Iv[4][INPUT];
    #pragma unroll
    for (int c = 0; c < 4; c++) {
        const float* srow = seeds + ((size_t)s * HIDDEN + (h0 + c)) * DD;
        float sd[DD];
        #pragma unroll
        for (int e = 0; e < DD; e++) sd[e] = srow[e];
        float comb[DD];
        #pragma unroll
        for (int d = 0; d < DD; d++) {
            float v = mc[d];
            for (int e = 0; e <= d; e++) v = fmaf(Lc[d][e], sd[e], v);
            comb[d] = v;
        }
        m0v[c] = comb[0]; m1v[c] = comb[1];
        n0v[c] = comb[2]; n1v[c] = comb[3];
        #pragma unroll
        for (int i = 0; i < INPUT; i++) Iv[c][i] = comb[4 + i];
    }

    // ---- pack loop constants (identical to R13) ----
    float4 N0 = make_float4(n0v[0] * QSCALE, n0v[1] * QSCALE,
                            n0v[2] * QSCALE, n0v[3] * QSCALE);
    float4 N1 = make_float4(n1v[0] * QSCALE, n1v[1] * QSCALE,
                            n1v[2] * QSCALE, n1v[3] * QSCALE);

    const float KQ = K1_F * QINV;
    const u64 M0A = pk2(m0v[0] * KQ, m0v[1] * KQ);
    const u64 M0B = pk2(m0v[2] * KQ, m0v[3] * KQ);
    const u64 M1A = pk2(m1v[0] * KQ, m1v[1] * KQ);
    const u64 M1B = pk2(m1v[2] * KQ, m1v[3] * KQ);

    u64 IwA[INPUT], IwB[INPUT];
    #pragma unroll
    for (int i = 0; i < INPUT; i++) {
        IwA[i] = pk2(ALPHA_F * Iv[0][i], ALPHA_F * Iv[1][i]);
        IwB[i] = pk2(ALPHA_F * Iv[2][i], ALPHA_F * Iv[3][i]);
    }

    const float* xb = x + (size_t)b * SEQ * INPUT;
    float* ob = out + (size_t)b * SEQ * OUTK;     // full output rows
    const float K1S = K1_F * QINV;
    const u64 C9 = pk2(0.9f, 0.9f);
    const u64 ZU = 0ull;

    __shared__ __align__(16) u64 isp[2][4];       // [parity][warp]: {iq0,iq1}

    u64 hA = ZU, hB = ZU;                         // packed (h0,h1),(h2,h3)
    float oa = 0.0f, obv = 0.0f;                  // rank scans (all threads)
    float accx = 0.0f;                            // x-only scan (lanes 2..9)
    const bool store_lane = (wid == 3) && (lane < OUTK);
    const bool is0 = (lane == 0), is1 = (lane == 1);
    const float* xgl = xb + ((lane - 2) & 7);     // this lane's x column

    float4 xA0 = *(const float4*)(xb + 0), xB0 = *(const float4*)(xb + 4);
    float4 xA1 = *(const float4*)(xb + 8), xB1 = *(const float4*)(xb + 12);

    #define RNN_STEP(PAR, T, XA, XB)                                              \
    {                                                                             \
        /* x column for the fused output scan (L1 broadcast hit, off-chain) */    \
        float xg = ALPHA_F * xgl[(size_t)(T) * INPUT];                            \
        float2 hx = up2(hA), hy = up2(hB);                                        \
        float th0 = fast_tanh(hx.x);                                              \
        float th1 = fast_tanh(hx.y);                                              \
        float th2 = fast_tanh(hy.x);                                              \
        float th3 = fast_tanh(hy.y);                                              \
        float q0 = fmaf(N0.x, th0, N0.y * th1) + fmaf(N0.z, th2, N0.w * th3);     \
        float q1 = fmaf(N1.x, th0, N1.y * th1) + fmaf(N1.z, th2, N1.w * th3);     \
        int iq0 = __float2int_rn(q0);                                             \
        int iq1 = __float2int_rn(q1);                                             \
        iq0 = __reduce_add_sync(0xffffffffu, iq0);                                \
        iq1 = __reduce_add_sync(0xffffffffu, iq1);                                \
        if (lane == 0)                                                            \
            isp[PAR][wid] = ((u64)(unsigned)iq0 << 32) | (unsigned)iq1;           \
        /* shadow work: aix + decay applied to h (p-independent) */               \
        u64 xd0 = pk2(XA.x, XA.x), xd1 = pk2(XA.y, XA.y);                         \
        u64 xd2 = pk2(XA.z, XA.z), xd3 = pk2(XA.w, XA.w);                         \
        u64 xd4 = pk2(XB.x, XB.x), xd5 = pk2(XB.y, XB.y);                         \
        u64 xd6 = pk2(XB.z, XB.z), xd7 = pk2(XB.w, XB.w);                         \
        u64 aA = fma2(IwA[0], xd0, ZU);                                           \
        u64 aB = fma2(IwB[0], xd0, ZU);                                           \
        aA = fma2(IwA[1], xd1, aA);  aB = fma2(IwB[1], xd1, aB);                  \
        aA = fma2(IwA[2], xd2, aA);  aB = fma2(IwB[2], xd2, aB);                  \
        aA = fma2(IwA[3], xd3, aA);  aB = fma2(IwB[3], xd3, aB);                  \
        aA = fma2(IwA[4], xd4, aA);  aB = fma2(IwB[4], xd4, aB);                  \
        aA = fma2(IwA[5], xd5, aA);  aB = fma2(IwB[5], xd5, aB);                  \
        aA = fma2(IwA[6], xd6, aA);  aB = fma2(IwB[6], xd6, aB);                  \
        aA = fma2(IwA[7], xd7, aA);  aB = fma2(IwB[7], xd7, aB);                  \
        hA = fma2(C9, hA, aA);   /* h' = 0.9h + aix (p-independent) */            \
        hB = fma2(C9, hB, aB);                                                    \
        /* x-only output scan (bit-identical to the old xout math) */             \
        accx = fmaf(0.9f, accx, xg);                                              \
        __syncthreads();                                                          \
        ulonglong2 w01 = *(const ulonglong2*)&isp[PAR][0];                        \
        ulonglong2 w23 = *(const ulonglong2*)&isp[PAR][2];                        \
        int s0 = (int)(unsigned)(w01.x >> 32) + (int)(unsigned)(w01.y >> 32)      \
               + (int)(unsigned)(w23.x >> 32) + (int)(unsigned)(w23.y >> 32);     \
        int s1 = (int)(unsigned)w01.x + (int)(unsigned)w01.y                      \
               + (int)(unsigned)w23.x + (int)(unsigned)w23.y;                     \
        float p0 = (float)s0;                                                     \
        float p1 = (float)s1;                                                     \
        u64 p0d = pk2(p0, p0), p1d = pk2(p1, p1);                                 \
        hA = fma2(M0A, p0d, fma2(M1A, p1d, hA));                                  \
        hB = fma2(M0B, p0d, fma2(M1B, p1d, hB));                                  \
        oa  = fmaf(0.9f, oa,  K1S * p0);   /* all threads: symmetric streams */   \
        obv = fmaf(0.9f, obv, K1S * p1);                                          \
        float oval = is0 ? oa : (is1 ? obv : accx);                               \
        if (store_lane) ob[(size_t)(T) * OUTK + lane] = oval;                     \
    }

    for (int t = 0; t < SEQ; t += 2) {
        int tf = (t + 2 <= SEQ - 2) ? t + 2 : SEQ - 2;
        float4 nA0 = *(const float4*)(xb + (size_t)tf * INPUT);
        float4 nB0 = *(const float4*)(xb + (size_t)tf * INPUT + 4);
        float4 nA1 = *(const float4*)(xb + (size_t)(tf + 1) * INPUT);
        float4 nB1 = *(const float4*)(xb + (size_t)(tf + 1) * INPUT + 4);

        RNN_STEP(0, t,     xA0, xB0);
        RNN_STEP(1, t + 1, xA1, xB1);

        xA0 = nA0; xB0 = nB0; xA1 = nA1; xB1 = nB1;
    }
    #undef RNN_STEP
}

// ---------------- launch: ONE kernel ----------------
extern "C" void kernel_launch(void* const* d_in, const int* in_sizes, int n_in,
                              void* d_out, int out_size) {
    const float* x     = (const float*)d_in[0];   // (64,2048,8)
    const float* means = (const float*)d_in[1];   // (2,12)
    const float* L     = (const float*)d_in[2];   // (2,12,12)
    const float* mw    = (const float*)d_in[3];   // (2,)
    const float* seeds = (const float*)d_in[4];   // (4,512,12)
    const int*   cs    = (const int*)d_in[5];     // (64,)
    float* out = (float*)d_out;                   // (64,2048,10)

    rnn_kernel<<<BATCH, 128>>>(x, means, L, mw, seeds, cs, out);
}